// round 15
// baseline (speedup 1.0000x reference)
#include <cuda_runtime.h>
#include <cuda_bf16.h>
#include <cstdint>
#include <cstddef>

// B=8, S=1024, D=512, H=8, qdim=vdim=64, n=H*B=64
// d_out = out [8,1024,512] ++ heatmap [64,1024,1024]

// ---------------- scratch globals (bf16 pairs stored as u32 words) ------------
__device__ uint32_t g_qhi32[64ull * 1024 * 32], g_qlo32[64ull * 1024 * 32];
__device__ uint32_t g_khi32[64ull * 1024 * 32], g_klo32[64ull * 1024 * 32];
__device__ uint32_t g_vhi32[64ull * 1024 * 32], g_vlo32[64ull * 1024 * 32];
__device__ uint32_t g_wvhi32[8192ull * 256], g_wvlo32[8192ull * 256];
__device__ __nv_bfloat16 g_xhi[8192ull * 512], g_xlo[8192ull * 512];
__device__ __nv_bfloat16 g_wth[4][512 * 512], g_wtl[4][512 * 512];

// ---------------- helpers ------------------------------------------------------
__device__ __forceinline__ void mma16816(float* c, const uint32_t* a, const uint32_t* b) {
    asm volatile(
        "mma.sync.aligned.m16n8k16.row.col.f32.bf16.bf16.f32 "
        "{%0,%1,%2,%3}, {%4,%5,%6,%7}, {%8,%9}, {%0,%1,%2,%3};"
        : "+f"(c[0]), "+f"(c[1]), "+f"(c[2]), "+f"(c[3])
        : "r"(a[0]), "r"(a[1]), "r"(a[2]), "r"(a[3]), "r"(b[0]), "r"(b[1]));
}
__device__ __forceinline__ uint32_t packbf(float lo, float hi) {
    uint32_t r;
    asm("cvt.rn.bf16x2.f32 %0, %1, %2;" : "=r"(r) : "f"(hi), "f"(lo));
    return r;
}
__device__ __forceinline__ void split2(float a, float b, uint32_t& hw, uint32_t& lw) {
    uint32_t h = packbf(a, b);
    __nv_bfloat162 h2 = *reinterpret_cast<__nv_bfloat162*>(&h);
    float ra = a - __low2float(h2);
    float rb = b - __high2float(h2);
    hw = h;
    lw = packbf(ra, rb);
}
__device__ __forceinline__ uint32_t smem_u32(const void* p) {
    uint32_t a;
    asm("{ .reg .u64 t; cvta.to.shared.u64 t, %1; cvt.u32.u64 %0, t; }" : "=r"(a) : "l"(p));
    return a;
}
__device__ __forceinline__ void cpasync16(uint32_t saddr, const void* gptr) {
    asm volatile("cp.async.ca.shared.global [%0], [%1], 16;" :: "r"(saddr), "l"(gptr));
}
#define CP_COMMIT() asm volatile("cp.async.commit_group;" ::: "memory")
#define CP_WAIT(n) asm volatile("cp.async.wait_group %0;" :: "n"(n) : "memory")
__device__ __forceinline__ void ldm_x4(uint32_t* r, uint32_t addr) {
    asm volatile("ldmatrix.sync.aligned.m8n8.x4.shared.b16 {%0,%1,%2,%3}, [%4];"
                 : "=r"(r[0]), "=r"(r[1]), "=r"(r[2]), "=r"(r[3]) : "r"(addr));
}
__device__ __forceinline__ void ldm_x4_t(uint32_t* r, uint32_t addr) {
    asm volatile("ldmatrix.sync.aligned.m8n8.x4.trans.shared.b16 {%0,%1,%2,%3}, [%4];"
                 : "=r"(r[0]), "=r"(r[1]), "=r"(r[2]), "=r"(r[3]) : "r"(addr));
}
__device__ __forceinline__ void stg_cs_v2(float* p, float x, float y) {
    asm volatile("st.global.cs.v2.f32 [%0], {%1, %2};" :: "l"(p), "f"(x), "f"(y) : "memory");
}

// ---------------- fused conversion kernel --------------------------------------
__global__ void conv_all(const float* __restrict__ X,
                         const float* __restrict__ W0, const float* __restrict__ W1,
                         const float* __restrict__ W2, const float* __restrict__ W3) {
    if (blockIdx.z == 4) {
        const int bflat = blockIdx.y * 16 + blockIdx.x;
        const int t = threadIdx.y * 32 + threadIdx.x;
        size_t base = ((size_t)bflat * 1024 + t) * 4;
#pragma unroll
        for (int it = 0; it < 4; it++) {
            size_t i = base + (size_t)it * 1048576;
            float4 v = *(const float4*)(X + i);
            uint32_t h0, l0, h1, l1;
            split2(v.x, v.y, h0, l0);
            split2(v.z, v.w, h1, l1);
            *(uint32_t*)(g_xhi + i) = h0;
            *(uint32_t*)(g_xhi + i + 2) = h1;
            *(uint32_t*)(g_xlo + i) = l0;
            *(uint32_t*)(g_xlo + i + 2) = l1;
        }
        return;
    }
    __shared__ float t[32][33];
    const int widx = blockIdx.z;
    const float* W = (widx == 0) ? W0 : (widx == 1) ? W1 : (widx == 2) ? W2 : W3;
    int k = blockIdx.y * 32 + threadIdx.y;
    int n = blockIdx.x * 32 + threadIdx.x;
    t[threadIdx.y][threadIdx.x] = W[(size_t)k * 512 + n];
    __syncthreads();
    int n2 = blockIdx.x * 32 + threadIdx.y;
    int k2 = blockIdx.y * 32 + threadIdx.x;
    float v = t[threadIdx.x][threadIdx.y];
    __nv_bfloat16 h = __float2bfloat16_rn(v);
    g_wth[widx][(size_t)n2 * 512 + k2] = h;
    g_wtl[widx][(size_t)n2 * 512 + k2] = __float2bfloat16_rn(v - __bfloat162float(h));
}

// ---------------- HMMA split-bf16 GEMM (cp.async + ldmatrix, 2 CTA/SM) --------
#define TPAD 40
#define TG_ARR (128 * TPAD)
#define TG_STAGE (4 * TG_ARR)
#define TG_SMEM_BYTES (2 * TG_STAGE * 2)

__device__ __forceinline__ void tg_issue(uint32_t sb, int stage,
                                         const __nv_bfloat16* __restrict__ Ah,
                                         const __nv_bfloat16* __restrict__ Al,
                                         const __nv_bfloat16* __restrict__ Bh,
                                         const __nv_bfloat16* __restrict__ Bl,
                                         int m0, int n0, int k0, int tid) {
    const int row = tid >> 1, half = tid & 1;
    const uint32_t base = sb + stage * (TG_STAGE * 2);
    const uint32_t doff = (uint32_t)(row * TPAD + half * 16) * 2;
    const __nv_bfloat16* srcs[4] = {
        Ah + (size_t)(m0 + row) * 512 + k0 + half * 16,
        Al + (size_t)(m0 + row) * 512 + k0 + half * 16,
        Bh + (size_t)(n0 + row) * 512 + k0 + half * 16,
        Bl + (size_t)(n0 + row) * 512 + k0 + half * 16};
#pragma unroll
    for (int a = 0; a < 4; a++) {
        uint32_t d = base + a * (TG_ARR * 2) + doff;
        cpasync16(d, srcs[a]);
        cpasync16(d + 16, (const char*)srcs[a] + 16);
    }
}

__global__ __launch_bounds__(256, 2) void tgemm(int asel, int widx0,
                                                const float* __restrict__ bz0,
                                                const float* __restrict__ bz1,
                                                const float* __restrict__ bz2,
                                                float* __restrict__ outp, int mode0) {
    extern __shared__ __nv_bfloat16 smem[];
    const uint32_t sb = smem_u32(smem);

    const int z = blockIdx.z;
    const int widx = widx0 + z;
    const int mode = mode0 ? mode0 + z : 0;
    const float* bias = (z == 0) ? bz0 : (z == 1) ? bz1 : bz2;

    const int tid = threadIdx.x;
    const int wid = tid >> 5, lane = tid & 31;
    const int gid = lane >> 2, tig = lane & 3;
    const int wm0 = (wid >> 2) << 6;
    const int wn0 = (wid & 3) << 5;
    const int n0 = blockIdx.x << 7, m0 = blockIdx.y << 7;

    const int lrow = lane & 7;
    const uint32_t aoff = (uint32_t)(wm0 + ((lane >> 3) & 1) * 8 + lrow) * TPAD +
                          (lane >> 4) * 8;
    const uint32_t boff = (uint32_t)(2 + (lane >> 4)) * TG_ARR +
                          (uint32_t)(wn0 + lrow) * TPAD + ((lane >> 3) & 1) * 8;

    const __nv_bfloat16* Ah = asel ? (const __nv_bfloat16*)g_wvhi32 : g_xhi;
    const __nv_bfloat16* Al = asel ? (const __nv_bfloat16*)g_wvlo32 : g_xlo;
    const __nv_bfloat16* Bh = g_wth[widx];
    const __nv_bfloat16* Bl = g_wtl[widx];

    float acc[4][4][4];
#pragma unroll
    for (int i = 0; i < 4; i++)
#pragma unroll
        for (int j = 0; j < 4; j++)
#pragma unroll
            for (int e = 0; e < 4; e++) acc[i][j][e] = 0.f;

    tg_issue(sb, 0, Ah, Al, Bh, Bl, m0, n0, 0, tid);
    CP_COMMIT();

    for (int c = 0; c < 16; c++) {
        __syncthreads();
        if (c + 1 < 16) {
            tg_issue(sb, (c + 1) & 1, Ah, Al, Bh, Bl, m0, n0, (c + 1) << 5, tid);
            CP_COMMIT();
            CP_WAIT(1);
        } else {
            CP_WAIT(0);
        }
        __syncthreads();

        const uint32_t stb = sb + (c & 1) * (TG_STAGE * 2);
#pragma unroll
        for (int ks = 0; ks < 32; ks += 16) {
            uint32_t ah[4][4], al[4][4], bhl[4][4];
#pragma unroll
            for (int i = 0; i < 4; i++) {
                ldm_x4(ah[i], stb + (aoff + i * (16 * TPAD) + ks) * 2);
                ldm_x4(al[i], stb + (TG_ARR + aoff + i * (16 * TPAD) + ks) * 2);
            }
#pragma unroll
            for (int j = 0; j < 4; j++)
                ldm_x4(bhl[j], stb + (boff + j * (8 * TPAD) + ks) * 2);
#pragma unroll
            for (int i = 0; i < 4; i++)
#pragma unroll
                for (int j = 0; j < 4; j++) {
                    mma16816(acc[i][j], ah[i], bhl[j]);      // hi*hi
                    mma16816(acc[i][j], ah[i], bhl[j] + 2);  // hi*lo
                    mma16816(acc[i][j], al[i], bhl[j]);      // lo*hi
                }
        }
    }

    uint32_t* qh = (mode == 1) ? g_qhi32 : (mode == 2) ? g_khi32 : g_vhi32;
    uint32_t* ql = (mode == 1) ? g_qlo32 : (mode == 2) ? g_klo32 : g_vlo32;
#pragma unroll
    for (int i = 0; i < 4; i++) {
        const int r = m0 + wm0 + (i << 4) + gid;
#pragma unroll
        for (int j = 0; j < 4; j++) {
            const int col = n0 + wn0 + (j << 3) + (tig << 1);
            const float b0 = bias[col], b1 = bias[col + 1];
            float w00 = acc[i][j][0] + b0, w01 = acc[i][j][1] + b1;
            float w10 = acc[i][j][2] + b0, w11 = acc[i][j][3] + b1;
            if (mode == 0) {
                stg_cs_v2(outp + (size_t)r * 512 + col, w00, w01);
                stg_cs_v2(outp + (size_t)(r + 8) * 512 + col, w10, w11);
            } else {
                const int h = col >> 6, d = col & 63;
                const int bb = r >> 10, s = r & 1023;
                size_t w = (((size_t)(h * 8 + bb)) << 15) + ((size_t)s << 5) + (d >> 1);
                uint32_t hw, lw;
                split2(w00, w01, hw, lw);
                qh[w] = hw; ql[w] = lw;
                split2(w10, w11, hw, lw);
                qh[w + 256] = hw; ql[w + 256] = lw;
            }
        }
    }
}

// ---------------- tensorized fused attention + heatmap ------------------------
// Diagonal-block (tb==rb) warp-uniform skipping: warp wid only has live
// (unmasked) score columns for j < 2*wid+2 and live P rows for kt <= wid.
// Skipped contributions are exactly zero -> bit-identical results.
#define AT_P 36
#define AT_SKL 4608
#define AT_SVH 9216
#define AT_SVL 13824
#define AT_STW 18432
#define AT_SMEM_BYTES (2 * AT_STW * 4)

__device__ __forceinline__ void at_issue(uint32_t sb, int stage, uint32_t nbase,
                                         int t0, bool withV, int tid) {
    const uint32_t stb = sb + stage * (AT_STW * 4);
#pragma unroll
    for (int i = 0; i < 4; i++) {
        const int c = tid + (i << 8);
        const int row = c >> 3, seg = c & 7;
        const uint32_t w4 = (uint32_t)(row * AT_P + seg * 4) * 4;
        const uint32_t goff = nbase + ((t0 + row) << 5) + (seg << 2);
        cpasync16(stb + w4, g_khi32 + goff);
        cpasync16(stb + AT_SKL * 4 + w4, g_klo32 + goff);
        if (withV) {
            cpasync16(stb + AT_SVH * 4 + w4, g_vhi32 + goff);
            cpasync16(stb + AT_SVL * 4 + w4, g_vlo32 + goff);
        }
    }
}

__global__ __launch_bounds__(256) void attn_kernel(float* __restrict__ heat) {
    extern __shared__ uint32_t sm[];
    const uint32_t sb = smem_u32(sm);

    const int tid = threadIdx.x;
    const int wid = tid >> 5, lane = tid & 31;
    const int gid = lane >> 2, tig = lane & 3;
    const int rb = blockIdx.x, n = blockIdx.y;
    const int r0 = rb << 7, wr = wid << 4;
    const int hh = n >> 3, bb = n & 7;
    const uint32_t nbase = n << 15;

    const int sel = lane >> 3, lrow = lane & 7;
    const uint32_t kfl = ((sel & 2) ? AT_SKL : 0) + lrow * AT_P + ((sel & 1) << 2);
    const uint32_t vfl = ((sel & 2) ? AT_SVL : AT_SVH) + (((sel & 1) << 3) + lrow) * AT_P;

    {
        const uint32_t qstb = sb + AT_STW * 4;
#pragma unroll
        for (int i = 0; i < 4; i++) {
            const int c = tid + (i << 8);
            const int row = c >> 3, seg = c & 7;
            const uint32_t w4 = (uint32_t)(row * AT_P + seg * 4) * 4;
            const uint32_t goff = nbase + ((r0 + row) << 5) + (seg << 2);
            cpasync16(qstb + w4, g_qhi32 + goff);
            cpasync16(qstb + AT_SKL * 4 + w4, g_qlo32 + goff);
        }
    }
    CP_COMMIT();
    at_issue(sb, 0, nbase, 0, true, tid);
    CP_COMMIT();
    CP_WAIT(1);
    __syncthreads();

    uint32_t qhf[4][4], qlf[4][4];
    {
        const uint32_t* sQh = sm + AT_STW;
        const uint32_t* sQl = sm + AT_STW + AT_SKL;
#pragma unroll
        for (int kc = 0; kc < 4; kc++) {
            int b0 = (wr + gid) * AT_P + (kc << 3) + tig;
            int b1 = (wr + gid + 8) * AT_P + (kc << 3) + tig;
            qhf[kc][0] = sQh[b0]; qhf[kc][1] = sQh[b1];
            qhf[kc][2] = sQh[b0 + 4]; qhf[kc][3] = sQh[b1 + 4];
            qlf[kc][0] = sQl[b0]; qlf[kc][1] = sQl[b1];
            qlf[kc][2] = sQl[b0 + 4]; qlf[kc][3] = sQl[b1 + 4];
        }
    }
    __syncthreads();

    float m0 = -1e30f, m1 = -1e30f, l0 = 0.f, l1 = 0.f;
    float oacc[8][4];
#pragma unroll
    for (int j = 0; j < 8; j++)
#pragma unroll
        for (int e = 0; e < 4; e++) oacc[j][e] = 0.f;

    const int row0 = r0 + wr + gid, row1 = row0 + 8;

    for (int tb = 0; tb < 8; tb++) {
        const int t0 = tb << 7;
        const bool causal = (tb <= rb);
        const bool diag = (tb == rb);
        const int jm = diag ? (2 * wid + 2) : 16;   // warp-uniform live j bound
        const int ktm = diag ? (wid + 1) : 8;       // warp-uniform live kt bound
        if (tb + 1 < 8) {
            at_issue(sb, (tb + 1) & 1, nbase, (tb + 1) << 7, (tb + 1) <= rb, tid);
            CP_COMMIT();
            CP_WAIT(1);
        } else {
            CP_WAIT(0);
        }
        __syncthreads();
        const uint32_t stb = sb + (tb & 1) * (AT_STW * 4);

        // ---- S = Q K^T (full: heatmap needs all raw scores) ----
        float sacc[16][4];
#pragma unroll
        for (int j = 0; j < 16; j++)
#pragma unroll
            for (int e = 0; e < 4; e++) sacc[j][e] = 0.f;
#pragma unroll
        for (int kc = 0; kc < 4; kc++) {
#pragma unroll
            for (int j = 0; j < 16; j++) {
                uint32_t kf[4];
                ldm_x4(kf, stb + (kfl + j * (8 * AT_P) + (kc << 3)) * 4);
                mma16816(sacc[j], qhf[kc], kf);
                mma16816(sacc[j], qlf[kc], kf);
                mma16816(sacc[j], qhf[kc], kf + 2);
            }
        }

        {
            float* h0p = heat + ((size_t)n << 20) + ((size_t)row0 << 10) + t0 + (tig << 1);
            float* h1p = heat + ((size_t)n << 20) + ((size_t)row1 << 10) + t0 + (tig << 1);
#pragma unroll
            for (int j = 0; j < 16; j++) {
                stg_cs_v2(h0p + (j << 3), sacc[j][0], sacc[j][1]);
                stg_cs_v2(h1p + (j << 3), sacc[j][2], sacc[j][3]);
            }
        }

        if (causal) {
            if (diag) {
#pragma unroll
                for (int j = 0; j < 16; j++) {
                    if (j >= jm) break;
                    const int c0 = t0 + (j << 3) + (tig << 1);
                    if (c0 > row0) sacc[j][0] = -1e30f;
                    if (c0 + 1 > row0) sacc[j][1] = -1e30f;
                    if (c0 > row1) sacc[j][2] = -1e30f;
                    if (c0 + 1 > row1) sacc[j][3] = -1e30f;
                }
            }

            float vm0 = -1e30f, vm1 = -1e30f;
#pragma unroll
            for (int j = 0; j < 16; j++) {
                if (j >= jm) break;
                vm0 = fmaxf(vm0, fmaxf(sacc[j][0], sacc[j][1]));
                vm1 = fmaxf(vm1, fmaxf(sacc[j][2], sacc[j][3]));
            }
            vm0 = fmaxf(vm0, __shfl_xor_sync(0xffffffffu, vm0, 1));
            vm0 = fmaxf(vm0, __shfl_xor_sync(0xffffffffu, vm0, 2));
            vm1 = fmaxf(vm1, __shfl_xor_sync(0xffffffffu, vm1, 1));
            vm1 = fmaxf(vm1, __shfl_xor_sync(0xffffffffu, vm1, 2));
            const float mn0 = fmaxf(m0, vm0), mn1 = fmaxf(m1, vm1);
            const float sc0 = __expf(m0 - mn0), sc1 = __expf(m1 - mn1);
            m0 = mn0; m1 = mn1;
            float rs0 = 0.f, rs1 = 0.f;
#pragma unroll
            for (int j = 0; j < 16; j++) {
                if (j >= jm) break;
                sacc[j][0] = __expf(sacc[j][0] - mn0);
                sacc[j][1] = __expf(sacc[j][1] - mn0);
                sacc[j][2] = __expf(sacc[j][2] - mn1);
                sacc[j][3] = __expf(sacc[j][3] - mn1);
                rs0 += sacc[j][0] + sacc[j][1];
                rs1 += sacc[j][2] + sacc[j][3];
            }
            rs0 += __shfl_xor_sync(0xffffffffu, rs0, 1);
            rs0 += __shfl_xor_sync(0xffffffffu, rs0, 2);
            rs1 += __shfl_xor_sync(0xffffffffu, rs1, 1);
            rs1 += __shfl_xor_sync(0xffffffffu, rs1, 2);
            l0 = l0 * sc0 + rs0;
            l1 = l1 * sc1 + rs1;
#pragma unroll
            for (int j = 0; j < 8; j++) {
                oacc[j][0] *= sc0; oacc[j][1] *= sc0;
                oacc[j][2] *= sc1; oacc[j][3] *= sc1;
            }

#pragma unroll
            for (int kt = 0; kt < 8; kt++) {
                if (kt >= ktm) break;
                uint32_t ph[4], pl[4];
                split2(sacc[2 * kt][0], sacc[2 * kt][1], ph[0], pl[0]);
                split2(sacc[2 * kt][2], sacc[2 * kt][3], ph[1], pl[1]);
                split2(sacc[2 * kt + 1][0], sacc[2 * kt + 1][1], ph[2], pl[2]);
                split2(sacc[2 * kt + 1][2], sacc[2 * kt + 1][3], ph[3], pl[3]);
#pragma unroll
                for (int j = 0; j < 8; j++) {
                    uint32_t vf[4];
                    ldm_x4_t(vf, stb + (vfl + kt * (16 * AT_P) + (j << 2)) * 4);
                    mma16816(oacc[j], ph, vf);
                    mma16816(oacc[j], pl, vf);
                    mma16816(oacc[j], ph, vf + 2);
                }
            }
        }
        __syncthreads();
    }

    const float i0 = 1.0f / l0, i1 = 1.0f / l1;
    const uint32_t wb0 = ((bb << 10) + row0) * 256 + (hh << 5) + tig;
    const uint32_t wb1 = ((bb << 10) + row1) * 256 + (hh << 5) + tig;
#pragma unroll
    for (int j = 0; j < 8; j++) {
        uint32_t hw, lw;
        split2(oacc[j][0] * i0, oacc[j][1] * i0, hw, lw);
        g_wvhi32[wb0 + (j << 2)] = hw;
        g_wvlo32[wb0 + (j << 2)] = lw;
        split2(oacc[j][2] * i1, oacc[j][3] * i1, hw, lw);
        g_wvhi32[wb1 + (j << 2)] = hw;
        g_wvlo32[wb1 + (j << 2)] = lw;
    }
}

// ---------------- launch ------------------------------------------------------
extern "C" void kernel_launch(void* const* d_in, const int* in_sizes, int n_in,
                              void* d_out, int out_size) {
    const float* x  = (const float*)d_in[0];
    const float* Wq = (const float*)d_in[1];
    const float* bq = (const float*)d_in[2];
    const float* Wk = (const float*)d_in[3];
    const float* bk = (const float*)d_in[4];
    const float* Wv = (const float*)d_in[5];
    const float* bv = (const float*)d_in[6];
    const float* Wo = (const float*)d_in[7];
    const float* bo = (const float*)d_in[8];

    float* out = (float*)d_out;
    float* heat = out + (size_t)8 * 1024 * 512;

    cudaFuncSetAttribute(attn_kernel, cudaFuncAttributeMaxDynamicSharedMemorySize,
                         AT_SMEM_BYTES);
    cudaFuncSetAttribute(tgemm, cudaFuncAttributeMaxDynamicSharedMemorySize,
                         TG_SMEM_BYTES);

    conv_all<<<dim3(16, 16, 5), dim3(32, 32)>>>(x, Wq, Wk, Wv, Wo);

    tgemm<<<dim3(4, 64, 3), 256, TG_SMEM_BYTES>>>(0, 0, bq, bk, bv, nullptr, 1);
    attn_kernel<<<dim3(8, 64), 256, AT_SMEM_BYTES>>>(heat);
    tgemm<<<dim3(4, 64, 1), 256, TG_SMEM_BYTES>>>(1, 3, bo, nullptr, nullptr, out, 0);
}

// round 16
// speedup vs baseline: 1.0170x; 1.0170x over previous
#include <cuda_runtime.h>
#include <cuda_bf16.h>
#include <cstdint>
#include <cstddef>

// B=8, S=1024, D=512, H=8, qdim=vdim=64, n=H*B=64
// d_out = out [8,1024,512] ++ heatmap [64,1024,1024]

// ---------------- scratch globals (bf16 pairs stored as u32 words) ------------
__device__ uint32_t g_qhi32[64ull * 1024 * 32], g_qlo32[64ull * 1024 * 32];
__device__ uint32_t g_khi32[64ull * 1024 * 32], g_klo32[64ull * 1024 * 32];
__device__ uint32_t g_vhi32[64ull * 1024 * 32], g_vlo32[64ull * 1024 * 32];
__device__ uint32_t g_wvhi32[8192ull * 256], g_wvlo32[8192ull * 256];
__device__ __nv_bfloat16 g_xhi[8192ull * 512], g_xlo[8192ull * 512];
__device__ __nv_bfloat16 g_wth[4][512 * 512], g_wtl[4][512 * 512];

// ---------------- helpers ------------------------------------------------------
__device__ __forceinline__ void mma16816(float* c, const uint32_t* a, const uint32_t* b) {
    asm volatile(
        "mma.sync.aligned.m16n8k16.row.col.f32.bf16.bf16.f32 "
        "{%0,%1,%2,%3}, {%4,%5,%6,%7}, {%8,%9}, {%0,%1,%2,%3};"
        : "+f"(c[0]), "+f"(c[1]), "+f"(c[2]), "+f"(c[3])
        : "r"(a[0]), "r"(a[1]), "r"(a[2]), "r"(a[3]), "r"(b[0]), "r"(b[1]));
}
__device__ __forceinline__ uint32_t packbf(float lo, float hi) {
    uint32_t r;
    asm("cvt.rn.bf16x2.f32 %0, %1, %2;" : "=r"(r) : "f"(hi), "f"(lo));
    return r;
}
__device__ __forceinline__ void split2(float a, float b, uint32_t& hw, uint32_t& lw) {
    uint32_t h = packbf(a, b);
    __nv_bfloat162 h2 = *reinterpret_cast<__nv_bfloat162*>(&h);
    float ra = a - __low2float(h2);
    float rb = b - __high2float(h2);
    hw = h;
    lw = packbf(ra, rb);
}
__device__ __forceinline__ uint32_t smem_u32(const void* p) {
    uint32_t a;
    asm("{ .reg .u64 t; cvta.to.shared.u64 t, %1; cvt.u32.u64 %0, t; }" : "=r"(a) : "l"(p));
    return a;
}
__device__ __forceinline__ void cpasync16(uint32_t saddr, const void* gptr) {
    asm volatile("cp.async.ca.shared.global [%0], [%1], 16;" :: "r"(saddr), "l"(gptr));
}
#define CP_COMMIT() asm volatile("cp.async.commit_group;" ::: "memory")
#define CP_WAIT(n) asm volatile("cp.async.wait_group %0;" :: "n"(n) : "memory")
__device__ __forceinline__ void ldm_x4(uint32_t* r, uint32_t addr) {
    asm volatile("ldmatrix.sync.aligned.m8n8.x4.shared.b16 {%0,%1,%2,%3}, [%4];"
                 : "=r"(r[0]), "=r"(r[1]), "=r"(r[2]), "=r"(r[3]) : "r"(addr));
}
__device__ __forceinline__ void ldm_x4_t(uint32_t* r, uint32_t addr) {
    asm volatile("ldmatrix.sync.aligned.m8n8.x4.trans.shared.b16 {%0,%1,%2,%3}, [%4];"
                 : "=r"(r[0]), "=r"(r[1]), "=r"(r[2]), "=r"(r[3]) : "r"(addr));
}
__device__ __forceinline__ void stg_cs_v2(float* p, float x, float y) {
    asm volatile("st.global.cs.v2.f32 [%0], {%1, %2};" :: "l"(p), "f"(x), "f"(y) : "memory");
}

// ---------------- fused conversion kernel --------------------------------------
__global__ void conv_all(const float* __restrict__ X,
                         const float* __restrict__ W0, const float* __restrict__ W1,
                         const float* __restrict__ W2, const float* __restrict__ W3) {
    if (blockIdx.z == 4) {
        const int bflat = blockIdx.y * 16 + blockIdx.x;
        const int t = threadIdx.y * 32 + threadIdx.x;
        size_t base = ((size_t)bflat * 1024 + t) * 4;
#pragma unroll
        for (int it = 0; it < 4; it++) {
            size_t i = base + (size_t)it * 1048576;
            float4 v = *(const float4*)(X + i);
            uint32_t h0, l0, h1, l1;
            split2(v.x, v.y, h0, l0);
            split2(v.z, v.w, h1, l1);
            *(uint32_t*)(g_xhi + i) = h0;
            *(uint32_t*)(g_xhi + i + 2) = h1;
            *(uint32_t*)(g_xlo + i) = l0;
            *(uint32_t*)(g_xlo + i + 2) = l1;
        }
        return;
    }
    __shared__ float t[32][33];
    const int widx = blockIdx.z;
    const float* W = (widx == 0) ? W0 : (widx == 1) ? W1 : (widx == 2) ? W2 : W3;
    int k = blockIdx.y * 32 + threadIdx.y;
    int n = blockIdx.x * 32 + threadIdx.x;
    t[threadIdx.y][threadIdx.x] = W[(size_t)k * 512 + n];
    __syncthreads();
    int n2 = blockIdx.x * 32 + threadIdx.y;
    int k2 = blockIdx.y * 32 + threadIdx.x;
    float v = t[threadIdx.x][threadIdx.y];
    __nv_bfloat16 h = __float2bfloat16_rn(v);
    g_wth[widx][(size_t)n2 * 512 + k2] = h;
    g_wtl[widx][(size_t)n2 * 512 + k2] = __float2bfloat16_rn(v - __bfloat162float(h));
}

// ---------------- HMMA split-bf16 GEMM (cp.async + ldmatrix, 2 CTA/SM) --------
#define TPAD 40
#define TG_ARR (128 * TPAD)
#define TG_STAGE (4 * TG_ARR)
#define TG_SMEM_BYTES (2 * TG_STAGE * 2)

__device__ __forceinline__ void tg_issue(uint32_t sb, int stage,
                                         const __nv_bfloat16* __restrict__ Ah,
                                         const __nv_bfloat16* __restrict__ Al,
                                         const __nv_bfloat16* __restrict__ Bh,
                                         const __nv_bfloat16* __restrict__ Bl,
                                         int m0, int n0, int k0, int tid) {
    const int row = tid >> 1, half = tid & 1;
    const uint32_t base = sb + stage * (TG_STAGE * 2);
    const uint32_t doff = (uint32_t)(row * TPAD + half * 16) * 2;
    const __nv_bfloat16* srcs[4] = {
        Ah + (size_t)(m0 + row) * 512 + k0 + half * 16,
        Al + (size_t)(m0 + row) * 512 + k0 + half * 16,
        Bh + (size_t)(n0 + row) * 512 + k0 + half * 16,
        Bl + (size_t)(n0 + row) * 512 + k0 + half * 16};
#pragma unroll
    for (int a = 0; a < 4; a++) {
        uint32_t d = base + a * (TG_ARR * 2) + doff;
        cpasync16(d, srcs[a]);
        cpasync16(d + 16, (const char*)srcs[a] + 16);
    }
}

__global__ __launch_bounds__(256, 2) void tgemm(int asel, int widx0,
                                                const float* __restrict__ bz0,
                                                const float* __restrict__ bz1,
                                                const float* __restrict__ bz2,
                                                float* __restrict__ outp, int mode0) {
    extern __shared__ __nv_bfloat16 smem[];
    const uint32_t sb = smem_u32(smem);

    const int z = blockIdx.z;
    const int widx = widx0 + z;
    const int mode = mode0 ? mode0 + z : 0;
    const float* bias = (z == 0) ? bz0 : (z == 1) ? bz1 : bz2;

    const int tid = threadIdx.x;
    const int wid = tid >> 5, lane = tid & 31;
    const int gid = lane >> 2, tig = lane & 3;
    const int wm0 = (wid >> 2) << 6;
    const int wn0 = (wid & 3) << 5;
    const int n0 = blockIdx.x << 7, m0 = blockIdx.y << 7;

    const int lrow = lane & 7;
    const uint32_t aoff = (uint32_t)(wm0 + ((lane >> 3) & 1) * 8 + lrow) * TPAD +
                          (lane >> 4) * 8;
    const uint32_t boff = (uint32_t)(2 + (lane >> 4)) * TG_ARR +
                          (uint32_t)(wn0 + lrow) * TPAD + ((lane >> 3) & 1) * 8;

    const __nv_bfloat16* Ah = asel ? (const __nv_bfloat16*)g_wvhi32 : g_xhi;
    const __nv_bfloat16* Al = asel ? (const __nv_bfloat16*)g_wvlo32 : g_xlo;
    const __nv_bfloat16* Bh = g_wth[widx];
    const __nv_bfloat16* Bl = g_wtl[widx];

    float acc[4][4][4];
#pragma unroll
    for (int i = 0; i < 4; i++)
#pragma unroll
        for (int j = 0; j < 4; j++)
#pragma unroll
            for (int e = 0; e < 4; e++) acc[i][j][e] = 0.f;

    tg_issue(sb, 0, Ah, Al, Bh, Bl, m0, n0, 0, tid);
    CP_COMMIT();

    for (int c = 0; c < 16; c++) {
        __syncthreads();
        if (c + 1 < 16) {
            tg_issue(sb, (c + 1) & 1, Ah, Al, Bh, Bl, m0, n0, (c + 1) << 5, tid);
            CP_COMMIT();
            CP_WAIT(1);
        } else {
            CP_WAIT(0);
        }
        __syncthreads();

        const uint32_t stb = sb + (c & 1) * (TG_STAGE * 2);
#pragma unroll
        for (int ks = 0; ks < 32; ks += 16) {
            uint32_t ah[4][4], al[4][4], bhl[4][4];
#pragma unroll
            for (int i = 0; i < 4; i++) {
                ldm_x4(ah[i], stb + (aoff + i * (16 * TPAD) + ks) * 2);
                ldm_x4(al[i], stb + (TG_ARR + aoff + i * (16 * TPAD) + ks) * 2);
            }
#pragma unroll
            for (int j = 0; j < 4; j++)
                ldm_x4(bhl[j], stb + (boff + j * (8 * TPAD) + ks) * 2);
#pragma unroll
            for (int i = 0; i < 4; i++)
#pragma unroll
                for (int j = 0; j < 4; j++) {
                    mma16816(acc[i][j], ah[i], bhl[j]);      // hi*hi
                    mma16816(acc[i][j], ah[i], bhl[j] + 2);  // hi*lo
                    mma16816(acc[i][j], al[i], bhl[j]);      // lo*hi
                }
        }
    }

    uint32_t* qh = (mode == 1) ? g_qhi32 : (mode == 2) ? g_khi32 : g_vhi32;
    uint32_t* ql = (mode == 1) ? g_qlo32 : (mode == 2) ? g_klo32 : g_vlo32;
#pragma unroll
    for (int i = 0; i < 4; i++) {
        const int r = m0 + wm0 + (i << 4) + gid;
#pragma unroll
        for (int j = 0; j < 4; j++) {
            const int col = n0 + wn0 + (j << 3) + (tig << 1);
            const float b0 = bias[col], b1 = bias[col + 1];
            float w00 = acc[i][j][0] + b0, w01 = acc[i][j][1] + b1;
            float w10 = acc[i][j][2] + b0, w11 = acc[i][j][3] + b1;
            if (mode == 0) {
                stg_cs_v2(outp + (size_t)r * 512 + col, w00, w01);
                stg_cs_v2(outp + (size_t)(r + 8) * 512 + col, w10, w11);
            } else {
                const int h = col >> 6, d = col & 63;
                const int bb = r >> 10, s = r & 1023;
                size_t w = (((size_t)(h * 8 + bb)) << 15) + ((size_t)s << 5) + (d >> 1);
                uint32_t hw, lw;
                split2(w00, w01, hw, lw);
                qh[w] = hw; ql[w] = lw;
                split2(w10, w11, hw, lw);
                qh[w + 256] = hw; ql[w + 256] = lw;
            }
        }
    }
}

// ---------------- tensorized fused attention + heatmap ------------------------
// Causal section interleaves exp (MUFU) of chunk kt with P*V MMAs (tensor) of
// the same chunk, giving intra-warp pipe overlap. Value order is unchanged ->
// bit-exact vs the R13 kernel.
#define AT_P 36
#define AT_SKL 4608
#define AT_SVH 9216
#define AT_SVL 13824
#define AT_STW 18432
#define AT_SMEM_BYTES (2 * AT_STW * 4)

__device__ __forceinline__ void at_issue(uint32_t sb, int stage, uint32_t nbase,
                                         int t0, bool withV, int tid) {
    const uint32_t stb = sb + stage * (AT_STW * 4);
#pragma unroll
    for (int i = 0; i < 4; i++) {
        const int c = tid + (i << 8);
        const int row = c >> 3, seg = c & 7;
        const uint32_t w4 = (uint32_t)(row * AT_P + seg * 4) * 4;
        const uint32_t goff = nbase + ((t0 + row) << 5) + (seg << 2);
        cpasync16(stb + w4, g_khi32 + goff);
        cpasync16(stb + AT_SKL * 4 + w4, g_klo32 + goff);
        if (withV) {
            cpasync16(stb + AT_SVH * 4 + w4, g_vhi32 + goff);
            cpasync16(stb + AT_SVL * 4 + w4, g_vlo32 + goff);
        }
    }
}

__global__ __launch_bounds__(256) void attn_kernel(float* __restrict__ heat) {
    extern __shared__ uint32_t sm[];
    const uint32_t sb = smem_u32(sm);

    const int tid = threadIdx.x;
    const int wid = tid >> 5, lane = tid & 31;
    const int gid = lane >> 2, tig = lane & 3;
    const int rb = blockIdx.x, n = blockIdx.y;
    const int r0 = rb << 7, wr = wid << 4;
    const int hh = n >> 3, bb = n & 7;
    const uint32_t nbase = n << 15;

    const int sel = lane >> 3, lrow = lane & 7;
    const uint32_t kfl = ((sel & 2) ? AT_SKL : 0) + lrow * AT_P + ((sel & 1) << 2);
    const uint32_t vfl = ((sel & 2) ? AT_SVL : AT_SVH) + (((sel & 1) << 3) + lrow) * AT_P;

    {
        const uint32_t qstb = sb + AT_STW * 4;
#pragma unroll
        for (int i = 0; i < 4; i++) {
            const int c = tid + (i << 8);
            const int row = c >> 3, seg = c & 7;
            const uint32_t w4 = (uint32_t)(row * AT_P + seg * 4) * 4;
            const uint32_t goff = nbase + ((r0 + row) << 5) + (seg << 2);
            cpasync16(qstb + w4, g_qhi32 + goff);
            cpasync16(qstb + AT_SKL * 4 + w4, g_qlo32 + goff);
        }
    }
    CP_COMMIT();
    at_issue(sb, 0, nbase, 0, true, tid);
    CP_COMMIT();
    CP_WAIT(1);
    __syncthreads();

    uint32_t qhf[4][4], qlf[4][4];
    {
        const uint32_t* sQh = sm + AT_STW;
        const uint32_t* sQl = sm + AT_STW + AT_SKL;
#pragma unroll
        for (int kc = 0; kc < 4; kc++) {
            int b0 = (wr + gid) * AT_P + (kc << 3) + tig;
            int b1 = (wr + gid + 8) * AT_P + (kc << 3) + tig;
            qhf[kc][0] = sQh[b0]; qhf[kc][1] = sQh[b1];
            qhf[kc][2] = sQh[b0 + 4]; qhf[kc][3] = sQh[b1 + 4];
            qlf[kc][0] = sQl[b0]; qlf[kc][1] = sQl[b1];
            qlf[kc][2] = sQl[b0 + 4]; qlf[kc][3] = sQl[b1 + 4];
        }
    }
    __syncthreads();

    float m0 = -1e30f, m1 = -1e30f, l0 = 0.f, l1 = 0.f;
    float oacc[8][4];
#pragma unroll
    for (int j = 0; j < 8; j++)
#pragma unroll
        for (int e = 0; e < 4; e++) oacc[j][e] = 0.f;

    const int row0 = r0 + wr + gid, row1 = row0 + 8;

    for (int tb = 0; tb < 8; tb++) {
        const int t0 = tb << 7;
        const bool causal = (tb <= rb);
        if (tb + 1 < 8) {
            at_issue(sb, (tb + 1) & 1, nbase, (tb + 1) << 7, (tb + 1) <= rb, tid);
            CP_COMMIT();
            CP_WAIT(1);
        } else {
            CP_WAIT(0);
        }
        __syncthreads();
        const uint32_t stb = sb + (tb & 1) * (AT_STW * 4);

        float sacc[16][4];
#pragma unroll
        for (int j = 0; j < 16; j++)
#pragma unroll
            for (int e = 0; e < 4; e++) sacc[j][e] = 0.f;
#pragma unroll
        for (int kc = 0; kc < 4; kc++) {
#pragma unroll
            for (int j = 0; j < 16; j++) {
                uint32_t kf[4];
                ldm_x4(kf, stb + (kfl + j * (8 * AT_P) + (kc << 3)) * 4);
                mma16816(sacc[j], qhf[kc], kf);
                mma16816(sacc[j], qlf[kc], kf);
                mma16816(sacc[j], qhf[kc], kf + 2);
            }
        }

        {
            float* h0p = heat + ((size_t)n << 20) + ((size_t)row0 << 10) + t0 + (tig << 1);
            float* h1p = heat + ((size_t)n << 20) + ((size_t)row1 << 10) + t0 + (tig << 1);
#pragma unroll
            for (int j = 0; j < 16; j++) {
                stg_cs_v2(h0p + (j << 3), sacc[j][0], sacc[j][1]);
                stg_cs_v2(h1p + (j << 3), sacc[j][2], sacc[j][3]);
            }
        }

        if (causal) {
            if (tb == rb) {
#pragma unroll
                for (int j = 0; j < 16; j++) {
                    const int c0 = t0 + (j << 3) + (tig << 1);
                    if (c0 > row0) sacc[j][0] = -1e30f;
                    if (c0 + 1 > row0) sacc[j][1] = -1e30f;
                    if (c0 > row1) sacc[j][2] = -1e30f;
                    if (c0 + 1 > row1) sacc[j][3] = -1e30f;
                }
            }

            // row max (no exp needed)
            float vm0 = -1e30f, vm1 = -1e30f;
#pragma unroll
            for (int j = 0; j < 16; j++) {
                vm0 = fmaxf(vm0, fmaxf(sacc[j][0], sacc[j][1]));
                vm1 = fmaxf(vm1, fmaxf(sacc[j][2], sacc[j][3]));
            }
            vm0 = fmaxf(vm0, __shfl_xor_sync(0xffffffffu, vm0, 1));
            vm0 = fmaxf(vm0, __shfl_xor_sync(0xffffffffu, vm0, 2));
            vm1 = fmaxf(vm1, __shfl_xor_sync(0xffffffffu, vm1, 1));
            vm1 = fmaxf(vm1, __shfl_xor_sync(0xffffffffu, vm1, 2));
            const float mn0 = fmaxf(m0, vm0), mn1 = fmaxf(m1, vm1);
            const float sc0 = __expf(m0 - mn0), sc1 = __expf(m1 - mn1);
            m0 = mn0; m1 = mn1;
#pragma unroll
            for (int j = 0; j < 8; j++) {
                oacc[j][0] *= sc0; oacc[j][1] *= sc0;
                oacc[j][2] *= sc1; oacc[j][3] *= sc1;
            }

            // interleaved exp (MUFU) + split + P*V (tensor) per kt chunk
            float rs0 = 0.f, rs1 = 0.f;
#pragma unroll
            for (int kt = 0; kt < 8; kt++) {
                const int ja = 2 * kt, jb = 2 * kt + 1;
                sacc[ja][0] = __expf(sacc[ja][0] - mn0);
                sacc[ja][1] = __expf(sacc[ja][1] - mn0);
                sacc[ja][2] = __expf(sacc[ja][2] - mn1);
                sacc[ja][3] = __expf(sacc[ja][3] - mn1);
                rs0 += sacc[ja][0] + sacc[ja][1];
                rs1 += sacc[ja][2] + sacc[ja][3];
                sacc[jb][0] = __expf(sacc[jb][0] - mn0);
                sacc[jb][1] = __expf(sacc[jb][1] - mn0);
                sacc[jb][2] = __expf(sacc[jb][2] - mn1);
                sacc[jb][3] = __expf(sacc[jb][3] - mn1);
                rs0 += sacc[jb][0] + sacc[jb][1];
                rs1 += sacc[jb][2] + sacc[jb][3];

                uint32_t ph[4], pl[4];
                split2(sacc[ja][0], sacc[ja][1], ph[0], pl[0]);
                split2(sacc[ja][2], sacc[ja][3], ph[1], pl[1]);
                split2(sacc[jb][0], sacc[jb][1], ph[2], pl[2]);
                split2(sacc[jb][2], sacc[jb][3], ph[3], pl[3]);
#pragma unroll
                for (int j = 0; j < 8; j++) {
                    uint32_t vf[4];
                    ldm_x4_t(vf, stb + (vfl + kt * (16 * AT_P) + (j << 2)) * 4);
                    mma16816(oacc[j], ph, vf);
                    mma16816(oacc[j], pl, vf);
                    mma16816(oacc[j], ph, vf + 2);
                }
            }
            rs0 += __shfl_xor_sync(0xffffffffu, rs0, 1);
            rs0 += __shfl_xor_sync(0xffffffffu, rs0, 2);
            rs1 += __shfl_xor_sync(0xffffffffu, rs1, 1);
            rs1 += __shfl_xor_sync(0xffffffffu, rs1, 2);
            l0 = l0 * sc0 + rs0;
            l1 = l1 * sc1 + rs1;
        }
        __syncthreads();
    }

    const float i0 = 1.0f / l0, i1 = 1.0f / l1;
    const uint32_t wb0 = ((bb << 10) + row0) * 256 + (hh << 5) + tig;
    const uint32_t wb1 = ((bb << 10) + row1) * 256 + (hh << 5) + tig;
#pragma unroll
    for (int j = 0; j < 8; j++) {
        uint32_t hw, lw;
        split2(oacc[j][0] * i0, oacc[j][1] * i0, hw, lw);
        g_wvhi32[wb0 + (j << 2)] = hw;
        g_wvlo32[wb0 + (j << 2)] = lw;
        split2(oacc[j][2] * i1, oacc[j][3] * i1, hw, lw);
        g_wvhi32[wb1 + (j << 2)] = hw;
        g_wvlo32[wb1 + (j << 2)] = lw;
    }
}

// ---------------- launch ------------------------------------------------------
extern "C" void kernel_launch(void* const* d_in, const int* in_sizes, int n_in,
                              void* d_out, int out_size) {
    const float* x  = (const float*)d_in[0];
    const float* Wq = (const float*)d_in[1];
    const float* bq = (const float*)d_in[2];
    const float* Wk = (const float*)d_in[3];
    const float* bk = (const float*)d_in[4];
    const float* Wv = (const float*)d_in[5];
    const float* bv = (const float*)d_in[6];
    const float* Wo = (const float*)d_in[7];
    const float* bo = (const float*)d_in[8];

    float* out = (float*)d_out;
    float* heat = out + (size_t)8 * 1024 * 512;

    cudaFuncSetAttribute(attn_kernel, cudaFuncAttributeMaxDynamicSharedMemorySize,
                         AT_SMEM_BYTES);
    cudaFuncSetAttribute(tgemm, cudaFuncAttributeMaxDynamicSharedMemorySize,
                         TG_SMEM_BYTES);

    conv_all<<<dim3(16, 16, 5), dim3(32, 32)>>>(x, Wq, Wk, Wv, Wo);

    tgemm<<<dim3(4, 64, 3), 256, TG_SMEM_BYTES>>>(0, 0, bq, bk, bv, nullptr, 1);
    attn_kernel<<<dim3(8, 64), 256, AT_SMEM_BYTES>>>(heat);
    tgemm<<<dim3(4, 64, 1), 256, TG_SMEM_BYTES>>>(1, 3, bo, nullptr, nullptr, out, 0);
}